// round 10
// baseline (speedup 1.0000x reference)
#include <cuda_runtime.h>
#include <math.h>

#define THREADS 256
#define JT      256
#define RPT     2            // rows per thread; block covers THREADS*RPT rows

typedef unsigned long long ull;

// 12 fp64 accumulator slots: job*4 + (rem&3). Zero-initialized at module load;
// the last block resets them after reading so every graph replay starts from 0.
__device__ double   g_acc[12];
__device__ unsigned g_ticket = 0;

__device__ __forceinline__ float ex2f(float v) {
    float y;
    asm("ex2.approx.ftz.f32 %0, %1;" : "=f"(y) : "f"(v));
    return y;
}

__device__ __forceinline__ void red_relaxed_f64(double* p, double v) {
    asm volatile("red.relaxed.gpu.global.add.f64 [%0], %1;" :: "l"(p), "d"(v) : "memory");
}
__device__ __forceinline__ unsigned atom_acqrel_inc(unsigned* p) {
    unsigned old;
    asm volatile("atom.acq_rel.gpu.global.add.u32 %0, [%1], 1;"
                 : "=r"(old) : "l"(p) : "memory");
    return old;
}
__device__ __forceinline__ double ld_acquire_f64(const double* p) {
    double v;
    asm volatile("ld.acquire.gpu.global.f64 %0, [%1];" : "=d"(v) : "l"(p) : "memory");
    return v;
}

// Single fused kernel; grid enumerates ONLY non-empty tiles so the whole launch
// is one balanced wave (1056 blocks < 152 SMs * 8 resident).
// Job 0: xz, all iTiles*jSlabs tiles. Jobs 1/2 (xx, zz): upper-wedge tiles only
// (js >= 2*it), recovered from a linear wedge index.
__global__ void __launch_bounds__(THREADS) pair_kernel(
    const float* __restrict__ x, const float* __restrict__ z,
    const float* __restrict__ ks, const float* __restrict__ theta,
    float* __restrict__ out, int n)
{
    const int iTiles = n / (THREADS * RPT);   // 16
    const int jSlabs = n / JT;                // 32
    const int tpj = iTiles * jSlabs;          // 512
    // wedge tile count per sym job: sum_{it}(jSlabs-2it) = it*(jSlabs+1-it) at it=iTiles
    const int wedge = iTiles * (jSlabs + 1 - iTiles);   // 272

    const int b = blockIdx.x;
    const int tid = threadIdx.x;

    int job, it, js;
    if (b < tpj) {
        job = 0;
        it = b % iTiles;
        js = b / iTiles;
    } else {
        int u = b - tpj;
        job = 1 + u / wedge;
        u -= (job - 1) * wedge;
        // find it: base(it) = it*(jSlabs+1-it) <= u < base(it+1)
        int itv = 0;
        while (true) {
            int nb = (itv + 1) * (jSlabs + 1 - (itv + 1));
            if (nb > u) break;
            itv++;
        }
        it = itv;
        js = 2 * it + (u - it * (jSlabs + 1 - it));
    }

    // ---- Passthrough copy: out[0..3n) = x, out[3n..6n) = z, sliced by block ----
    {
        const int total = 6 * n;
        const int per = (total + gridDim.x - 1) / gridDim.x;
        const int start = b * per;
        const int stop = min(start + per, total);
        for (int idx = start + tid; idx < stop; idx += THREADS)
            out[idx] = (idx < 3 * n) ? x[idx] : z[idx - 3 * n];
    }

    const bool sym = (job >= 1);
    const int i0 = it * THREADS * RPT;
    const int j0 = js * JT;

    const float* A = (job == 2) ? z : x;
    const float* B = (job == 1) ? x : z;

    const float sc = sqrtf(1.4426950408889634f / ks[0]);   // sqrt(log2e / ks)

    // B slab, packed-pairs layout for f32x2 math:
    //   sB[2*g]   = (bx0, bx1, by0, by1)
    //   sB[2*g+1] = (bz0, bz1, w0,  w1)    w = -|b|^2 (scaled)
    __shared__ float4 sB[JT];
    for (int g = tid; g < JT / 2; g += THREADS) {
        int ja = j0 + 2 * g, jb = ja + 1;
        float b0x = B[3 * ja]     * sc, b0y = B[3 * ja + 1] * sc, b0z = B[3 * ja + 2] * sc;
        float b1x = B[3 * jb]     * sc, b1y = B[3 * jb + 1] * sc, b1z = B[3 * jb + 2] * sc;
        float w0 = -(b0x * b0x + b0y * b0y + b0z * b0z);
        float w1 = -(b1x * b1x + b1y * b1y + b1z * b1z);
        sB[2 * g]     = make_float4(b0x, b1x, b0y, b1y);
        sB[2 * g + 1] = make_float4(b0z, b1z, w0, w1);
    }

    // Two rows per thread: r0 = i0+tid, r1 = i0+THREADS+tid.
    const int r0 = i0 + tid;
    const int r1 = r0 + THREADS;
    const float a0x = A[3 * r0]     * sc * 2.f;
    const float a0y = A[3 * r0 + 1] * sc * 2.f;
    const float a0z = A[3 * r0 + 2] * sc * 2.f;
    const float a0w = -0.25f * (a0x * a0x + a0y * a0y + a0z * a0z);
    const float a1x = A[3 * r1]     * sc * 2.f;
    const float a1y = A[3 * r1 + 1] * sc * 2.f;
    const float a1z = A[3 * r1 + 2] * sc * 2.f;
    const float a1w = -0.25f * (a1x * a1x + a1y * a1y + a1z * a1z);
    __syncthreads();

    float acc00 = 0.f, acc01 = 0.f;   // row 0
    float acc10 = 0.f, acc11 = 0.f;   // row 1

    const bool boundary = sym && (js == 2 * it || js == 2 * it + 1);

    if (!boundary) {
        // Full tile: predicate-free packed loop, 2 cols x 2 rows per iteration.
        ull a0x2, a0y2, a0z2, a1x2, a1y2, a1z2;
        asm("mov.b64 %0, {%1,%1};" : "=l"(a0x2) : "f"(a0x));
        asm("mov.b64 %0, {%1,%1};" : "=l"(a0y2) : "f"(a0y));
        asm("mov.b64 %0, {%1,%1};" : "=l"(a0z2) : "f"(a0z));
        asm("mov.b64 %0, {%1,%1};" : "=l"(a1x2) : "f"(a1x));
        asm("mov.b64 %0, {%1,%1};" : "=l"(a1y2) : "f"(a1y));
        asm("mov.b64 %0, {%1,%1};" : "=l"(a1z2) : "f"(a1z));
        unsigned sb = (unsigned)__cvta_generic_to_shared(sB);
#pragma unroll 4
        for (int k2 = 0; k2 < JT / 2; k2++) {
            ull p0, p1, q0, q1, s, u;
            asm("ld.shared.v2.u64 {%0,%1},[%2];" : "=l"(p0), "=l"(p1) : "r"(sb + k2 * 32));
            asm("ld.shared.v2.u64 {%0,%1},[%2];" : "=l"(q0), "=l"(q1) : "r"(sb + k2 * 32 + 16));
            asm("fma.rn.f32x2 %0,%1,%2,%3;" : "=l"(s) : "l"(a0x2), "l"(p0), "l"(q1));
            asm("fma.rn.f32x2 %0,%1,%2,%0;" : "+l"(s) : "l"(a0y2), "l"(p1));
            asm("fma.rn.f32x2 %0,%1,%2,%0;" : "+l"(s) : "l"(a0z2), "l"(q0));
            asm("fma.rn.f32x2 %0,%1,%2,%3;" : "=l"(u) : "l"(a1x2), "l"(p0), "l"(q1));
            asm("fma.rn.f32x2 %0,%1,%2,%0;" : "+l"(u) : "l"(a1y2), "l"(p1));
            asm("fma.rn.f32x2 %0,%1,%2,%0;" : "+l"(u) : "l"(a1z2), "l"(q0));
            float s0, s1, u0, u1;
            asm("mov.b64 {%0,%1}, %2;" : "=f"(s0), "=f"(s1) : "l"(s));
            asm("mov.b64 {%0,%1}, %2;" : "=f"(u0), "=f"(u1) : "l"(u));
            acc00 += ex2f(s0);
            acc01 += ex2f(s1);
            acc10 += ex2f(u0);
            acc11 += ex2f(u1);
        }
    } else {
        // Boundary tiles: js==2it -> row0 predicated (k>tid), row1 below-diag (skip).
        //                 js==2it+1 -> row0 fully above diag, row1 predicated (k>tid).
        const bool lower = (js == 2 * it);
        const float* f = (const float*)sB;
#pragma unroll 4
        for (int k = 0; k < JT; k++) {
            int k2 = k >> 1, l = k & 1;
            float bx = f[8 * k2 + l];
            float by = f[8 * k2 + 2 + l];
            float bz = f[8 * k2 + 4 + l];
            float bw = f[8 * k2 + 6 + l];
            float s = fmaf(a0x, bx, bw);
            s = fmaf(a0y, by, s);
            s = fmaf(a0z, bz, s);
            float e0 = ex2f(s);
            float t = fmaf(a1x, bx, bw);
            t = fmaf(a1y, by, t);
            t = fmaf(a1z, bz, t);
            float e1 = ex2f(t);
            if (lower) {
                if (k > tid) acc00 += e0;          // row1 contributes nothing
            } else {
                acc00 += e0;                        // row0 fully above diagonal
                if (k > tid) acc10 += e1;
            }
        }
    }

    // Per-row factor 2^{aw}, then block reduce -> one fp64 RED per block.
    float acc = (acc00 + acc01) * ex2f(a0w) + (acc10 + acc11) * ex2f(a1w);
#pragma unroll
    for (int o = 16; o > 0; o >>= 1) acc += __shfl_xor_sync(0xffffffffu, acc, o);
    __shared__ float ws[THREADS / 32];
    const int lane = tid & 31;
    const int wid = tid >> 5;
    if (lane == 0) ws[wid] = acc;
    __syncthreads();
    if (tid == 0) {
        float s = 0.f;
#pragma unroll
        for (int w = 0; w < THREADS / 32; w++) s += ws[w];
        red_relaxed_f64(&g_acc[job * 4 + (b & 3)], (double)s);
    }

    // ---- Fence-free last-block epilogue (tid 0 only) ----
    if (tid != 0) return;
    unsigned t = atom_acqrel_inc(&g_ticket);   // release: orders the RED above
    if (t != gridDim.x - 1) return;

    // Last block: all REDs are visible (acquire side of the acq_rel ticket).
    double t0 = 0.0, t1 = 0.0, t2 = 0.0;       // xz, xx(upper), zz(upper)
#pragma unroll
    for (int k = 0; k < 4; k++) {
        t0 += ld_acquire_f64(&g_acc[k]);
        t1 += ld_acquire_f64(&g_acc[4 + k]);
        t2 += ld_acquire_f64(&g_acc[8 + k]);
    }
    double inv = 1.0 / sqrt(2.0 * 3.14159265358979323846 * (double)ks[0]);
    double nn = (double)n * (double)n;
    double mxz = t0 * inv / nn;
    double mxx = (2.0 * t1 + (double)n) * inv / nn;   // upper*2 + diagonal (exp(0)=1)
    double mzz = (2.0 * t2 + (double)n) * inv / nn;
    double r = log(sqrt(mxx * mzz + 1e-5) / (mxz + 1e-5));
    out[6 * n] = (float)(r * (double)theta[0]);

    // Reset for the next graph replay (ordered before kernel completion).
#pragma unroll
    for (int k = 0; k < 12; k++) g_acc[k] = 0.0;
    g_ticket = 0;
}

extern "C" void kernel_launch(void* const* d_in, const int* in_sizes, int n_in,
                              void* d_out, int out_size) {
    const float* x     = (const float*)d_in[0];
    const float* z     = (const float*)d_in[1];
    const float* ks    = (const float*)d_in[2];
    const float* theta = (const float*)d_in[3];
    float* out = (float*)d_out;

    const int n = in_sizes[0] / 3;            // 8192
    const int iTiles = n / (THREADS * RPT);   // 16
    const int jSlabs = n / JT;                // 32
    const int tpj = iTiles * jSlabs;          // 512
    const int wedge = iTiles * (jSlabs + 1 - iTiles);   // 272

    pair_kernel<<<tpj + 2 * wedge, THREADS>>>(x, z, ks, theta, out, n);
}

// round 11
// speedup vs baseline: 1.2774x; 1.2774x over previous
#include <cuda_runtime.h>
#include <math.h>

#define THREADS 256
#define JT      256
#define RPT     2            // rows per thread; block covers THREADS*RPT rows

typedef unsigned long long ull;

// 12 fp64 accumulator slots: job*4 + (b&3). Zero-initialized at module load;
// the last block resets them after reading so every graph replay starts from 0.
__device__ double   g_acc[12];
__device__ unsigned g_ticket = 0;

__device__ __forceinline__ float ex2f(float v) {
    float y;
    asm("ex2.approx.ftz.f32 %0, %1;" : "=f"(y) : "f"(v));
    return y;
}

__device__ __forceinline__ void red_relaxed_f64(double* p, double v) {
    asm volatile("red.relaxed.gpu.global.add.f64 [%0], %1;" :: "l"(p), "d"(v) : "memory");
}
__device__ __forceinline__ unsigned atom_acqrel_inc(unsigned* p) {
    unsigned old;
    asm volatile("atom.acq_rel.gpu.global.add.u32 %0, [%1], 1;"
                 : "=r"(old) : "l"(p) : "memory");
    return old;
}

// Single fused kernel; grid enumerates ONLY non-empty tiles so the whole launch
// is one balanced wave (1056 blocks < 152 SMs * 8 resident).
// Job 0: xz, all iTiles*jSlabs tiles. Jobs 1/2 (xx, zz): upper-wedge tiles only
// (js >= 2*it), recovered from a linear wedge index.
__global__ void __launch_bounds__(THREADS) pair_kernel(
    const float* __restrict__ x, const float* __restrict__ z,
    const float* __restrict__ ks, const float* __restrict__ theta,
    float* __restrict__ out, int n)
{
    const int iTiles = n / (THREADS * RPT);   // 16
    const int jSlabs = n / JT;                // 32
    const int tpj = iTiles * jSlabs;          // 512
    // wedge tile count per sym job: sum_{it}(jSlabs-2it) = iTiles*(jSlabs+1-iTiles)
    const int wedge = iTiles * (jSlabs + 1 - iTiles);   // 272

    const int b = blockIdx.x;
    const int tid = threadIdx.x;

    int job, it, js;
    if (b < tpj) {
        job = 0;
        it = b % iTiles;
        js = b / iTiles;
    } else {
        int u = b - tpj;
        job = 1 + u / wedge;
        u -= (job - 1) * wedge;
        // find it: base(it) = it*(jSlabs+1-it) <= u < base(it+1)
        int itv = 0;
        while (true) {
            int nb = (itv + 1) * (jSlabs + 1 - (itv + 1));
            if (nb > u) break;
            itv++;
        }
        it = itv;
        js = 2 * it + (u - it * (jSlabs + 1 - it));
    }

    // ---- Passthrough copy: out[0..3n) = x, out[3n..6n) = z, sliced by block ----
    {
        const int total = 6 * n;
        const int per = (total + gridDim.x - 1) / gridDim.x;
        const int start = b * per;
        const int stop = min(start + per, total);
        for (int idx = start + tid; idx < stop; idx += THREADS)
            out[idx] = (idx < 3 * n) ? x[idx] : z[idx - 3 * n];
    }

    const bool sym = (job >= 1);
    const int i0 = it * THREADS * RPT;
    const int j0 = js * JT;

    const float* A = (job == 2) ? z : x;
    const float* B = (job == 1) ? x : z;

    const float sc = sqrtf(1.4426950408889634f / ks[0]);   // sqrt(log2e / ks)

    // B slab, packed-pairs layout for f32x2 math:
    //   sB[2*g]   = (bx0, bx1, by0, by1)
    //   sB[2*g+1] = (bz0, bz1, w0,  w1)    w = -|b|^2 (scaled)
    __shared__ float4 sB[JT];
    for (int g = tid; g < JT / 2; g += THREADS) {
        int ja = j0 + 2 * g, jb = ja + 1;
        float b0x = B[3 * ja]     * sc, b0y = B[3 * ja + 1] * sc, b0z = B[3 * ja + 2] * sc;
        float b1x = B[3 * jb]     * sc, b1y = B[3 * jb + 1] * sc, b1z = B[3 * jb + 2] * sc;
        float w0 = -(b0x * b0x + b0y * b0y + b0z * b0z);
        float w1 = -(b1x * b1x + b1y * b1y + b1z * b1z);
        sB[2 * g]     = make_float4(b0x, b1x, b0y, b1y);
        sB[2 * g + 1] = make_float4(b0z, b1z, w0, w1);
    }

    // Two rows per thread: r0 = i0+tid, r1 = i0+THREADS+tid.
    const int r0 = i0 + tid;
    const int r1 = r0 + THREADS;
    const float a0x = A[3 * r0]     * sc * 2.f;
    const float a0y = A[3 * r0 + 1] * sc * 2.f;
    const float a0z = A[3 * r0 + 2] * sc * 2.f;
    const float a0w = -0.25f * (a0x * a0x + a0y * a0y + a0z * a0z);
    const float a1x = A[3 * r1]     * sc * 2.f;
    const float a1y = A[3 * r1 + 1] * sc * 2.f;
    const float a1z = A[3 * r1 + 2] * sc * 2.f;
    const float a1w = -0.25f * (a1x * a1x + a1y * a1y + a1z * a1z);
    __syncthreads();

    float acc00 = 0.f, acc01 = 0.f;   // row 0
    float acc10 = 0.f, acc11 = 0.f;   // row 1

    const bool boundary = sym && (js == 2 * it || js == 2 * it + 1);

    if (!boundary) {
        // Full tile: predicate-free packed loop, 2 cols x 2 rows per iteration.
        ull a0x2, a0y2, a0z2, a1x2, a1y2, a1z2;
        asm("mov.b64 %0, {%1,%1};" : "=l"(a0x2) : "f"(a0x));
        asm("mov.b64 %0, {%1,%1};" : "=l"(a0y2) : "f"(a0y));
        asm("mov.b64 %0, {%1,%1};" : "=l"(a0z2) : "f"(a0z));
        asm("mov.b64 %0, {%1,%1};" : "=l"(a1x2) : "f"(a1x));
        asm("mov.b64 %0, {%1,%1};" : "=l"(a1y2) : "f"(a1y));
        asm("mov.b64 %0, {%1,%1};" : "=l"(a1z2) : "f"(a1z));
        unsigned sb = (unsigned)__cvta_generic_to_shared(sB);
#pragma unroll 8
        for (int k2 = 0; k2 < JT / 2; k2++) {
            ull p0, p1, q0, q1, s, u;
            asm("ld.shared.v2.u64 {%0,%1},[%2];" : "=l"(p0), "=l"(p1) : "r"(sb + k2 * 32));
            asm("ld.shared.v2.u64 {%0,%1},[%2];" : "=l"(q0), "=l"(q1) : "r"(sb + k2 * 32 + 16));
            asm("fma.rn.f32x2 %0,%1,%2,%3;" : "=l"(s) : "l"(a0x2), "l"(p0), "l"(q1));
            asm("fma.rn.f32x2 %0,%1,%2,%0;" : "+l"(s) : "l"(a0y2), "l"(p1));
            asm("fma.rn.f32x2 %0,%1,%2,%0;" : "+l"(s) : "l"(a0z2), "l"(q0));
            asm("fma.rn.f32x2 %0,%1,%2,%3;" : "=l"(u) : "l"(a1x2), "l"(p0), "l"(q1));
            asm("fma.rn.f32x2 %0,%1,%2,%0;" : "+l"(u) : "l"(a1y2), "l"(p1));
            asm("fma.rn.f32x2 %0,%1,%2,%0;" : "+l"(u) : "l"(a1z2), "l"(q0));
            float s0, s1, u0, u1;
            asm("mov.b64 {%0,%1}, %2;" : "=f"(s0), "=f"(s1) : "l"(s));
            asm("mov.b64 {%0,%1}, %2;" : "=f"(u0), "=f"(u1) : "l"(u));
            acc00 += ex2f(s0);
            acc01 += ex2f(s1);
            acc10 += ex2f(u0);
            acc11 += ex2f(u1);
        }
    } else {
        // Boundary tiles: js==2it -> row0 predicated (k>tid), row1 below-diag (skip).
        //                 js==2it+1 -> row0 fully above diag, row1 predicated (k>tid).
        const bool lower = (js == 2 * it);
        const float* f = (const float*)sB;
#pragma unroll 4
        for (int k = 0; k < JT; k++) {
            int k2 = k >> 1, l = k & 1;
            float bx = f[8 * k2 + l];
            float by = f[8 * k2 + 2 + l];
            float bz = f[8 * k2 + 4 + l];
            float bw = f[8 * k2 + 6 + l];
            float s = fmaf(a0x, bx, bw);
            s = fmaf(a0y, by, s);
            s = fmaf(a0z, bz, s);
            float e0 = ex2f(s);
            float t = fmaf(a1x, bx, bw);
            t = fmaf(a1y, by, t);
            t = fmaf(a1z, bz, t);
            float e1 = ex2f(t);
            if (lower) {
                if (k > tid) acc00 += e0;          // row1 contributes nothing
            } else {
                acc00 += e0;                        // row0 fully above diagonal
                if (k > tid) acc10 += e1;
            }
        }
    }

    // Per-row factor 2^{aw}, then block reduce -> one fp64 RED per block.
    float acc = (acc00 + acc01) * ex2f(a0w) + (acc10 + acc11) * ex2f(a1w);
#pragma unroll
    for (int o = 16; o > 0; o >>= 1) acc += __shfl_xor_sync(0xffffffffu, acc, o);
    __shared__ float ws[THREADS / 32];
    const int lane = tid & 31;
    const int wid = tid >> 5;
    if (lane == 0) ws[wid] = acc;
    __syncthreads();
    if (tid == 0) {
        float s = 0.f;
#pragma unroll
        for (int w = 0; w < THREADS / 32; w++) s += ws[w];
        red_relaxed_f64(&g_acc[job * 4 + (b & 3)], (double)s);
    }

    // ---- Fence-free last-block epilogue (tid 0 only) ----
    if (tid != 0) return;
    unsigned t = atom_acqrel_inc(&g_ticket);   // acq_rel RMW: release our RED,
    if (t != gridDim.x - 1) return;            // acquire all prior releases (RMW chain)

    // All 12 loads are independent (MLP=12) -> one L2 round trip, not 12 serial
    // acquire loads. Visibility is guaranteed by the acq_rel ticket RMW above.
    double v[12];
#pragma unroll
    for (int k = 0; k < 12; k++) v[k] = __ldcg(&g_acc[k]);

    double t0 = (v[0] + v[1]) + (v[2] + v[3]);      // xz
    double t1 = (v[4] + v[5]) + (v[6] + v[7]);      // xx (upper)
    double t2 = (v[8] + v[9]) + (v[10] + v[11]);    // zz (upper)

    double inv = 1.0 / sqrt(2.0 * 3.14159265358979323846 * (double)ks[0]);
    double nn = (double)n * (double)n;
    double mxz = t0 * inv / nn;
    double mxx = (2.0 * t1 + (double)n) * inv / nn;   // upper*2 + diagonal (exp(0)=1)
    double mzz = (2.0 * t2 + (double)n) * inv / nn;
    double r = 0.5 * log(mxx * mzz + 1e-5) - log(mxz + 1e-5);
    out[6 * n] = (float)(r * (double)theta[0]);

    // Reset for the next graph replay (ordered before kernel completion).
#pragma unroll
    for (int k = 0; k < 12; k++) g_acc[k] = 0.0;
    g_ticket = 0;
}

extern "C" void kernel_launch(void* const* d_in, const int* in_sizes, int n_in,
                              void* d_out, int out_size) {
    const float* x     = (const float*)d_in[0];
    const float* z     = (const float*)d_in[1];
    const float* ks    = (const float*)d_in[2];
    const float* theta = (const float*)d_in[3];
    float* out = (float*)d_out;

    const int n = in_sizes[0] / 3;            // 8192
    const int iTiles = n / (THREADS * RPT);   // 16
    const int jSlabs = n / JT;                // 32
    const int tpj = iTiles * jSlabs;          // 512
    const int wedge = iTiles * (jSlabs + 1 - iTiles);   // 272

    pair_kernel<<<tpj + 2 * wedge, THREADS>>>(x, z, ks, theta, out, n);
}